// round 5
// baseline (speedup 1.0000x reference)
#include <cuda_runtime.h>
#include <math.h>

#define NN   8192
#define FIN  128
#define FOUT 64
#define HEADS 2
#define CAP  512   // max neighbors per row we track (mean ~33, P(>512) ~ 0)

// Scratch (no allocations allowed): projected features + attention dot products
__device__ float g_feats[HEADS * NN * FOUT];   // [h][n][o], 4 MB
__device__ float g_as[HEADS * NN];             // a_self^T feats
__device__ float g_an[HEADS * NN];             // a_neigh^T feats

// ---------------------------------------------------------------------------
// K1: per-head projection GEMM feats = X @ W[h], fused a_s/a_n epilogue.
// Block: 64 threads = 16 row-groups(4 rows) x 4 o-chunks(16 outs).
// W[h] (32KB) staged in smem; X rows read via L1 (4x reuse across o-chunks).
// ---------------------------------------------------------------------------
__global__ __launch_bounds__(64) void gat_gemm(
    const float4* __restrict__ X4,        // [NN][FIN/4]
    const float4* __restrict__ W4,        // [H][FIN][FOUT/4]
    const float*  __restrict__ a_self,    // [H][FOUT]
    const float*  __restrict__ a_neigh)   // [H][FOUT]
{
    const int h   = blockIdx.y;
    const int n0  = blockIdx.x * 64;
    const int tid = threadIdx.x;
    const int rg  = tid >> 2;   // 0..15 -> 4-row group
    const int oc  = tid & 3;    // 0..3  -> 16-output chunk

    __shared__ float4 Wsh[FIN * (FOUT / 4)];   // 2048 float4 = 32 KB
    const float4* Wg = W4 + (size_t)h * (FIN * FOUT / 4);
    for (int i = tid; i < FIN * (FOUT / 4); i += 64) Wsh[i] = Wg[i];
    __syncthreads();

    float acc[4][16];
#pragma unroll
    for (int r = 0; r < 4; r++)
#pragma unroll
        for (int j = 0; j < 16; j++) acc[r][j] = 0.f;

    const int nbase = n0 + rg * 4;
#pragma unroll 4
    for (int f4 = 0; f4 < FIN / 4; f4++) {
        float4 xv[4];
#pragma unroll
        for (int r = 0; r < 4; r++)
            xv[r] = X4[(size_t)(nbase + r) * (FIN / 4) + f4];
#pragma unroll
        for (int ff = 0; ff < 4; ff++) {
#pragma unroll
            for (int jq = 0; jq < 4; jq++) {
                float4 w = Wsh[(f4 * 4 + ff) * (FOUT / 4) + oc * 4 + jq];
#pragma unroll
                for (int r = 0; r < 4; r++) {
                    float x = (ff == 0) ? xv[r].x : (ff == 1) ? xv[r].y
                            : (ff == 2) ? xv[r].z : xv[r].w;
                    acc[r][jq * 4 + 0] = fmaf(x, w.x, acc[r][jq * 4 + 0]);
                    acc[r][jq * 4 + 1] = fmaf(x, w.y, acc[r][jq * 4 + 1]);
                    acc[r][jq * 4 + 2] = fmaf(x, w.z, acc[r][jq * 4 + 2]);
                    acc[r][jq * 4 + 3] = fmaf(x, w.w, acc[r][jq * 4 + 3]);
                }
            }
        }
    }

    // Epilogue: write feats (float4) + fused attention dot products.
    const int obase = oc * 16;
    float4* F4 = reinterpret_cast<float4*>(g_feats);
#pragma unroll
    for (int r = 0; r < 4; r++) {
        const int n = nbase + r;
#pragma unroll
        for (int jq = 0; jq < 4; jq++) {
            float4 v = make_float4(acc[r][jq * 4 + 0], acc[r][jq * 4 + 1],
                                   acc[r][jq * 4 + 2], acc[r][jq * 4 + 3]);
            F4[((size_t)h * NN + n) * (FOUT / 4) + (obase >> 2) + jq] = v;
        }
        float ps = 0.f, pn = 0.f;
#pragma unroll
        for (int j = 0; j < 16; j++) {
            ps = fmaf(acc[r][j], a_self [h * FOUT + obase + j], ps);
            pn = fmaf(acc[r][j], a_neigh[h * FOUT + obase + j], pn);
        }
        // reduce across the 4 o-chunk lanes (lane bits 0-1)
        ps += __shfl_xor_sync(0xffffffffu, ps, 1);
        ps += __shfl_xor_sync(0xffffffffu, ps, 2);
        pn += __shfl_xor_sync(0xffffffffu, pn, 1);
        pn += __shfl_xor_sync(0xffffffffu, pn, 2);
        if (oc == 0) {
            g_as[h * NN + n] = ps;
            g_an[h * NN + n] = pn;
        }
    }
}

// ---------------------------------------------------------------------------
// K2: one block per row. Scan A row -> ordered neighbor list (deterministic
// prefix-scan compaction, no atomics), 2-head softmax over neighbors,
// weighted gather of feats, head-mean + bias + relu.
// ---------------------------------------------------------------------------
__global__ __launch_bounds__(256) void gat_agg(
    const float4* __restrict__ A4,       // [NN][NN/4]
    const float*  __restrict__ biases,   // [H][FOUT]
    float*        __restrict__ out)      // [NN][FOUT]
{
    const int row  = blockIdx.x;
    const int tid  = threadIdx.x;
    const int lane = tid & 31;
    const int wid  = tid >> 5;

    __shared__ int   sidx[CAP];
    __shared__ float sp0[CAP], sp1[CAP];
    __shared__ int   swsum[8];
    __shared__ float swA[8], swB[8];
    __shared__ float sb0, sb1;
    __shared__ int   s_nnz;
    __shared__ float saccb[256];

    // ---- Phase 1: scan A row (coalesced float4, front-batched for MLP) ----
    const float4* rowA = A4 + (size_t)row * (NN / 4);
    float4 v[8];
    int cnt = 0;
#pragma unroll
    for (int k = 0; k < 8; k++) {
        v[k] = __ldg(&rowA[tid + 256 * k]);
        cnt += (v[k].x != 0.f) + (v[k].y != 0.f) + (v[k].z != 0.f) + (v[k].w != 0.f);
    }
    // deterministic block exclusive scan of cnt
    int incl = cnt;
#pragma unroll
    for (int d = 1; d < 32; d <<= 1) {
        int t = __shfl_up_sync(0xffffffffu, incl, d);
        if (lane >= d) incl += t;
    }
    if (lane == 31) swsum[wid] = incl;
    __syncthreads();
    if (tid == 0) {
        int run = 0;
#pragma unroll
        for (int w = 0; w < 8; w++) { int t = swsum[w]; swsum[w] = run; run += t; }
        s_nnz = run;
    }
    __syncthreads();
    int offset = swsum[wid] + incl - cnt;
#pragma unroll
    for (int k = 0; k < 8; k++) {
        const int c = (tid + 256 * k) << 2;
        if (v[k].x != 0.f && offset < CAP) sidx[offset++] = c;
        if (v[k].y != 0.f && offset < CAP) sidx[offset++] = c + 1;
        if (v[k].z != 0.f && offset < CAP) sidx[offset++] = c + 2;
        if (v[k].w != 0.f && offset < CAP) sidx[offset++] = c + 3;
    }
    __syncthreads();
    const int nnz = min(s_nnz, CAP);

    // ---- Phase 2: logits + 2-head softmax over neighbors ----
    const float as0 = g_as[row];
    const float as1 = g_as[NN + row];
    float m0 = -1e30f, m1 = -1e30f;
    for (int k = tid; k < nnz; k += 256) {
        const int j = sidx[k];
        float l0 = as0 + g_an[j];
        float l1 = as1 + g_an[NN + j];
        l0 = (l0 > 0.f) ? l0 : 0.2f * l0;     // leaky relu
        l1 = (l1 > 0.f) ? l1 : 0.2f * l1;
        sp0[k] = l0; sp1[k] = l1;
        m0 = fmaxf(m0, l0); m1 = fmaxf(m1, l1);
    }
#pragma unroll
    for (int d = 16; d; d >>= 1) {
        m0 = fmaxf(m0, __shfl_xor_sync(0xffffffffu, m0, d));
        m1 = fmaxf(m1, __shfl_xor_sync(0xffffffffu, m1, d));
    }
    if (lane == 0) { swA[wid] = m0; swB[wid] = m1; }
    __syncthreads();
    if (tid == 0) {
        float a = swA[0], b = swB[0];
#pragma unroll
        for (int w = 1; w < 8; w++) { a = fmaxf(a, swA[w]); b = fmaxf(b, swB[w]); }
        sb0 = a; sb1 = b;
    }
    __syncthreads();
    m0 = sb0; m1 = sb1;

    float sum0 = 0.f, sum1 = 0.f;
    for (int k = tid; k < nnz; k += 256) {
        const float p0 = __expf(sp0[k] - m0);
        const float p1 = __expf(sp1[k] - m1);
        sp0[k] = p0; sp1[k] = p1;
        sum0 += p0; sum1 += p1;
    }
#pragma unroll
    for (int d = 16; d; d >>= 1) {
        sum0 += __shfl_xor_sync(0xffffffffu, sum0, d);
        sum1 += __shfl_xor_sync(0xffffffffu, sum1, d);
    }
    if (lane == 0) { swA[wid] = sum0; swB[wid] = sum1; }
    __syncthreads();
    if (tid == 0) {
        float a = 0.f, b = 0.f;
#pragma unroll
        for (int w = 0; w < 8; w++) { a += swA[w]; b += swB[w]; }
        sb0 = 1.f / a; sb1 = 1.f / b;
    }
    __syncthreads();
    const float inv0 = sb0, inv1 = sb1;

    // ---- Phase 3: weighted gather of feats, 2-way neighbor split ----
    const int s = tid >> 7;            // neighbor split half
    const int r = tid & 127;
    const int h = r >> 6;
    const int o = r & 63;
    const float* F  = g_feats + (size_t)h * NN * FOUT + o;
    const float* sp = h ? sp1 : sp0;
    float acc = 0.f;
#pragma unroll 4
    for (int k = s; k < nnz; k += 2) {
        acc = fmaf(sp[k], __ldg(&F[(size_t)sidx[k] * FOUT]), acc);
    }
    saccb[tid] = acc;
    __syncthreads();

    if (tid < 64) {
        const float o0 = (saccb[tid]      + saccb[128 + tid]) * inv0 + biases[tid];
        const float o1 = (saccb[64 + tid] + saccb[192 + tid]) * inv1 + biases[FOUT + tid];
        const float res = 0.5f * (o0 + o1);
        out[(size_t)row * FOUT + tid] = res > 0.f ? res : 0.f;
    }
}

// ---------------------------------------------------------------------------
extern "C" void kernel_launch(void* const* d_in, const int* in_sizes, int n_in,
                              void* d_out, int out_size)
{
    const float* X       = (const float*)d_in[0];   // [8192,128]
    const float* A       = (const float*)d_in[1];   // [8192,8192]
    const float* W       = (const float*)d_in[2];   // [2,128,64]
    const float* biases  = (const float*)d_in[3];   // [2,64]
    const float* a_self  = (const float*)d_in[4];   // [2,64]
    const float* a_neigh = (const float*)d_in[5];   // [2,64]
    float* out = (float*)d_out;                     // [8192,64]

    dim3 g1(NN / 64, HEADS);
    gat_gemm<<<g1, 64>>>((const float4*)X, (const float4*)W, a_self, a_neigh);
    gat_agg<<<NN, 256>>>((const float4*)A, biases, out);
}

// round 7
// speedup vs baseline: 1.5660x; 1.5660x over previous
#include <cuda_runtime.h>
#include <math.h>

#define NN    8192
#define FIN   128
#define FOUT  64
#define HEADS 2
#define WCAP  64      // per-warp neighbor cap (expected ~4/warp-segment)

// Scratch (no allocations allowed)
__device__ float g_feats[HEADS * NN * FOUT];   // [h][n][o]
__device__ float g_as[HEADS * NN];
__device__ float g_an[HEADS * NN];

// ---------------------------------------------------------------------------
// K1: projection GEMM, one head per block, 64 rows/block, 256 threads.
// Thread = 4 rows x 4 outputs (1 float4). W (32KB) in smem, 4x amortized.
// ---------------------------------------------------------------------------
__global__ __launch_bounds__(256) void gat_gemm(
    const float4* __restrict__ X4,        // [NN][FIN/4]
    const float4* __restrict__ W4,        // [H][FIN][FOUT/4]
    const float*  __restrict__ a_self,    // [H][FOUT]
    const float*  __restrict__ a_neigh)   // [H][FOUT]
{
    const int h   = blockIdx.y;
    const int n0  = blockIdx.x * 64;
    const int tid = threadIdx.x;
    const int rg  = tid >> 4;   // 0..15 : 4-row group
    const int oc  = tid & 15;   // 0..15 : one float4 of outputs

    __shared__ float4 Wsh[FIN * (FOUT / 4)];   // 2048 float4 = 32 KB
    const float4* Wg = W4 + (size_t)h * (FIN * FOUT / 4);
    for (int i = tid; i < FIN * (FOUT / 4); i += 256) Wsh[i] = Wg[i];
    __syncthreads();

    float acc[4][4];
#pragma unroll
    for (int r = 0; r < 4; r++)
#pragma unroll
        for (int j = 0; j < 4; j++) acc[r][j] = 0.f;

    const int nbase = n0 + rg * 4;
#pragma unroll 4
    for (int f4 = 0; f4 < FIN / 4; f4++) {
        float4 xv[4];
#pragma unroll
        for (int r = 0; r < 4; r++)
            xv[r] = __ldg(&X4[(size_t)(nbase + r) * (FIN / 4) + f4]);
#pragma unroll
        for (int ff = 0; ff < 4; ff++) {
            const float4 w = Wsh[(f4 * 4 + ff) * (FOUT / 4) + oc];
#pragma unroll
            for (int r = 0; r < 4; r++) {
                const float x = (ff == 0) ? xv[r].x : (ff == 1) ? xv[r].y
                              : (ff == 2) ? xv[r].z : xv[r].w;
                acc[r][0] = fmaf(x, w.x, acc[r][0]);
                acc[r][1] = fmaf(x, w.y, acc[r][1]);
                acc[r][2] = fmaf(x, w.z, acc[r][2]);
                acc[r][3] = fmaf(x, w.w, acc[r][3]);
            }
        }
    }

    // Epilogue: write feats + fused attention dot products.
    const int obase = oc * 4;
    float4* F4 = reinterpret_cast<float4*>(g_feats);
#pragma unroll
    for (int r = 0; r < 4; r++) {
        const int n = nbase + r;
        F4[((size_t)h * NN + n) * (FOUT / 4) + oc] =
            make_float4(acc[r][0], acc[r][1], acc[r][2], acc[r][3]);
        float ps = 0.f, pn = 0.f;
#pragma unroll
        for (int j = 0; j < 4; j++) {
            ps = fmaf(acc[r][j], a_self [h * FOUT + obase + j], ps);
            pn = fmaf(acc[r][j], a_neigh[h * FOUT + obase + j], pn);
        }
        // reduce across the 16 oc lanes (lane bits 0-3)
#pragma unroll
        for (int d = 1; d < 16; d <<= 1) {
            ps += __shfl_xor_sync(0xffffffffu, ps, d);
            pn += __shfl_xor_sync(0xffffffffu, pn, d);
        }
        if (oc == 0) {
            g_as[h * NN + n] = ps;
            g_an[h * NN + n] = pn;
        }
    }
}

// ---------------------------------------------------------------------------
// K2: one block per row. Warp-ballot scan with all-zero fast path,
// deterministic segmented compaction, 2-head softmax, weighted gather.
// ---------------------------------------------------------------------------
__global__ __launch_bounds__(256) void gat_agg(
    const float4* __restrict__ A4,       // [NN][NN/4]
    const float*  __restrict__ biases,   // [H][FOUT]
    float*        __restrict__ out)      // [NN][FOUT]
{
    const int row  = blockIdx.x;
    const int tid  = threadIdx.x;
    const int lane = tid & 31;
    const int w    = tid >> 5;

    __shared__ int   sidx[8 * WCAP];     // segmented per-warp lists
    __shared__ int   sjd [8 * WCAP];     // densely compacted indices
    __shared__ float sp0 [8 * WCAP], sp1[8 * WCAP];
    __shared__ int   scnt[8], soff[9];
    __shared__ float swA[8], swB[8];
    __shared__ float sb0v, sb1v;
    __shared__ float sacc0[256], sacc1[256];

    // ---- Phase 1: scan this row's slice (warp w owns 1024 elements) ----
    const float4* base = A4 + (size_t)row * (NN / 4) + w * 256 + lane;
    const unsigned lt = (1u << lane) - 1u;
    int wcnt = 0;
    float4 cur = __ldg(&base[0]);
#pragma unroll
    for (int step = 0; step < 8; step++) {
        float4 nxt = __ldg(&base[(step < 7 ? step + 1 : 7) * 32]);
        const bool nz = (cur.x + cur.y + cur.z + cur.w) != 0.f;  // A is 0/1
        const unsigned any = __ballot_sync(0xffffffffu, nz);
        if (any) {   // warp-uniform slow path (~rare: E[nnz]=0.5 per step)
            const unsigned m0 = __ballot_sync(0xffffffffu, cur.x != 0.f);
            const unsigned m1 = __ballot_sync(0xffffffffu, cur.y != 0.f);
            const unsigned m2 = __ballot_sync(0xffffffffu, cur.z != 0.f);
            const unsigned m3 = __ballot_sync(0xffffffffu, cur.w != 0.f);
            int o = wcnt + __popc(m0 & lt) + __popc(m1 & lt)
                         + __popc(m2 & lt) + __popc(m3 & lt);
            const int col = (w * 256 + step * 32 + lane) << 2;
            int* seg = sidx + w * WCAP;
            if (cur.x != 0.f && o < WCAP) seg[o++] = col;
            if (cur.y != 0.f && o < WCAP) seg[o++] = col + 1;
            if (cur.z != 0.f && o < WCAP) seg[o++] = col + 2;
            if (cur.w != 0.f && o < WCAP) seg[o++] = col + 3;
            wcnt += __popc(m0) + __popc(m1) + __popc(m2) + __popc(m3);
        }
        cur = nxt;
    }
    if (lane == 0) scnt[w] = min(wcnt, WCAP);
    __syncthreads();
    if (tid == 0) {
        int run = 0;
#pragma unroll
        for (int s = 0; s < 8; s++) { soff[s] = run; run += scnt[s]; }
        soff[8] = run;
    }
    __syncthreads();
    const int nnz = soff[8];

    // ---- Phase 2: compact + logits + max ----
    const float as0 = g_as[row];
    const float as1 = g_as[NN + row];
    float m0 = -1e30f, m1 = -1e30f;
#pragma unroll
    for (int k = tid; k < 8 * WCAP; k += 256) {
        const int s = k >> 6, i = k & (WCAP - 1);
        if (i < scnt[s]) {
            const int j = sidx[k];
            const int d = soff[s] + i;
            sjd[d] = j;
            float l0 = as0 + g_an[j];
            float l1 = as1 + g_an[NN + j];
            l0 = (l0 > 0.f) ? l0 : 0.2f * l0;
            l1 = (l1 > 0.f) ? l1 : 0.2f * l1;
            sp0[d] = l0; sp1[d] = l1;
            m0 = fmaxf(m0, l0); m1 = fmaxf(m1, l1);
        }
    }
#pragma unroll
    for (int d = 16; d; d >>= 1) {
        m0 = fmaxf(m0, __shfl_xor_sync(0xffffffffu, m0, d));
        m1 = fmaxf(m1, __shfl_xor_sync(0xffffffffu, m1, d));
    }
    if (lane == 0) { swA[w] = m0; swB[w] = m1; }
    __syncthreads();
    if (tid == 0) {
        float a = swA[0], b = swB[0];
#pragma unroll
        for (int s = 1; s < 8; s++) { a = fmaxf(a, swA[s]); b = fmaxf(b, swB[s]); }
        sb0v = a; sb1v = b;
    }
    __syncthreads();
    m0 = sb0v; m1 = sb1v;

    float sum0 = 0.f, sum1 = 0.f;
    for (int k = tid; k < nnz; k += 256) {
        const float p0 = __expf(sp0[k] - m0);
        const float p1 = __expf(sp1[k] - m1);
        sp0[k] = p0; sp1[k] = p1;
        sum0 += p0; sum1 += p1;
    }
#pragma unroll
    for (int d = 16; d; d >>= 1) {
        sum0 += __shfl_xor_sync(0xffffffffu, sum0, d);
        sum1 += __shfl_xor_sync(0xffffffffu, sum1, d);
    }
    if (lane == 0) { swA[w] = sum0; swB[w] = sum1; }
    __syncthreads();
    if (tid == 0) {
        float a = 0.f, b = 0.f;
#pragma unroll
        for (int s = 0; s < 8; s++) { a += swA[s]; b += swB[s]; }
        sb0v = 1.f / a; sb1v = 1.f / b;
    }
    __syncthreads();
    const float inv0 = sb0v, inv1 = sb1v;

    // ---- Phase 3: weighted gather, 4-way neighbor split, both heads ----
    const int s4 = tid >> 6;     // 0..3 neighbor stride offset
    const int o  = tid & 63;     // output channel
    const float* F0 = g_feats + o;
    const float* F1 = g_feats + (size_t)NN * FOUT + o;
    float a0 = 0.f, a1 = 0.f;
#pragma unroll 2
    for (int k = s4; k < nnz; k += 4) {
        const int j = sjd[k];
        a0 = fmaf(sp0[k], __ldg(F0 + (size_t)j * FOUT), a0);
        a1 = fmaf(sp1[k], __ldg(F1 + (size_t)j * FOUT), a1);
    }
    sacc0[tid] = a0;
    sacc1[tid] = a1;
    __syncthreads();

    if (tid < 64) {
        const float h0 = (sacc0[tid] + sacc0[64 + tid] + sacc0[128 + tid] + sacc0[192 + tid]) * inv0
                         + biases[tid];
        const float h1 = (sacc1[tid] + sacc1[64 + tid] + sacc1[128 + tid] + sacc1[192 + tid]) * inv1
                         + biases[FOUT + tid];
        const float res = 0.5f * (h0 + h1);
        out[(size_t)row * FOUT + tid] = res > 0.f ? res : 0.f;
    }
}

// ---------------------------------------------------------------------------
extern "C" void kernel_launch(void* const* d_in, const int* in_sizes, int n_in,
                              void* d_out, int out_size)
{
    const float* X       = (const float*)d_in[0];   // [8192,128]
    const float* A       = (const float*)d_in[1];   // [8192,8192]
    const float* W       = (const float*)d_in[2];   // [2,128,64]
    const float* biases  = (const float*)d_in[3];   // [2,64]
    const float* a_self  = (const float*)d_in[4];   // [2,64]
    const float* a_neigh = (const float*)d_in[5];   // [2,64]
    float* out = (float*)d_out;                     // [8192,64]

    dim3 g1(NN / 64, HEADS);
    gat_gemm<<<g1, 256>>>((const float4*)X, (const float4*)W, a_self, a_neigh);
    gat_agg<<<NN, 256>>>((const float4*)A, biases, out);
}